// round 9
// baseline (speedup 1.0000x reference)
#include <cuda_runtime.h>
#include <math.h>

#define RBF_K 32
#define HID   64
#define NG    8
#define NMAX  49152
#define EV2GPA 160.21766208f

#define TBL_N    16384
#define TBL_DMAX 16.0f
#define TBL_INVH ((float)TBL_N / TBL_DMAX)

// persistent device scratch (static — no runtime allocation)
__device__ float  g_scr[8 + 3 * NMAX + 72];   // [0:8) energy, [8:8+3N) gpos, then raw stress
__device__ float2 g_pts[TBL_N + 1];           // (e, dd) samples

__device__ __forceinline__ float fsigmoid(float z) {
    return __fdividef(1.0f, 1.0f + __expf(-z));
}

// ============================================================================
// Kernel 1: warp-per-point table build.
//   lane  = rbf index k for the exp stage
//   lane  = hidden pair (j, j+32) for layer 1 / (m, m+32) for layer 2
//   shuffle-broadcast loops do the cross contractions; butterflies reduce e, dd
// ============================================================================
#define BTPB   512
#define BGRID  296
// smem (floats): W1[K][H] row-major, W2[H][H], W2T[m][j], b1, b2, w3
#define S_W1  0
#define S_W2  (S_W1 + RBF_K*HID)
#define S_W2T (S_W2 + HID*HID)
#define S_B1  (S_W2T + HID*HID)
#define S_B2  (S_B1 + HID)
#define S_W3  (S_B2 + HID)
#define S_TOT (S_W3 + HID)

__global__ __launch_bounds__(BTPB, 2)
void build_pts_kernel(const float* __restrict__ W1, const float* __restrict__ b1,
                      const float* __restrict__ W2, const float* __restrict__ b2,
                      const float* __restrict__ W3, const float* __restrict__ b3,
                      const float* __restrict__ centers)
{
    __shared__ float sm[S_TOT];
    const int tid = threadIdx.x;
    for (int i = tid; i < RBF_K * HID; i += BTPB) sm[S_W1 + i] = W1[i];
    for (int i = tid; i < HID * HID; i += BTPB) {
        float w = W2[i];
        sm[S_W2 + i] = w;
        const int j = i >> 6, m = i & 63;
        sm[S_W2T + m * HID + j] = w;              // transpose for backward
    }
    if (tid < HID) {
        sm[S_B1 + tid] = b1[tid];
        sm[S_B2 + tid] = b2[tid];
        sm[S_W3 + tid] = W3[tid];
    }
    __syncthreads();

    const int lane = tid & 31;
    const int gwarp = (blockIdx.x * BTPB + tid) >> 5;
    const int nwarps = BGRID * (BTPB / 32);

    const float cme   = centers[lane];            // center for k = lane
    const float b3v   = b3[0];
    const float b1a   = sm[S_B1 + lane], b1b = sm[S_B1 + lane + 32];
    const float b2a   = sm[S_B2 + lane], b2b = sm[S_B2 + lane + 32];
    const float w3a   = sm[S_W3 + lane], w3b = sm[S_W3 + lane + 32];

    for (int p = gwarp; p <= TBL_N; p += nwarps) {
        const float d = (float)p * (TBL_DMAX / (float)TBL_N);

        // rbf_k, drbf_k for k = lane
        const float t  = d - cme;
        const float r  = __expf(-t * t);
        const float dr = -2.0f * t * r;

        // ---- layer 1: z1_j, u_j for j = lane, lane+32 ----
        float z1a = b1a, z1b = b1b, ua = 0.0f, ub = 0.0f;
        #pragma unroll
        for (int k = 0; k < 32; k++) {
            const float rk  = __shfl_sync(0xFFFFFFFFu, r,  k);
            const float drk = __shfl_sync(0xFFFFFFFFu, dr, k);
            const float wa = sm[S_W1 + k * HID + lane];
            const float wb = sm[S_W1 + k * HID + lane + 32];
            z1a += rk * wa;  z1b += rk * wb;
            ua  += drk * wa; ub  += drk * wb;
        }
        const float sga = fsigmoid(z1a), sgb = fsigmoid(z1b);
        const float ha = z1a * sga, hb = z1b * sgb;
        const float ta = (sga * (1.0f + z1a * (1.0f - sga))) * ua;   // silu'(z1)*u
        const float tb = (sgb * (1.0f + z1b * (1.0f - sgb))) * ub;

        // ---- layer 2: z2_m for m = lane, lane+32 ----
        float z2a = b2a, z2b = b2b;
        #pragma unroll
        for (int k = 0; k < 32; k++) {
            const float hka = __shfl_sync(0xFFFFFFFFu, ha, k);   // j = k
            const float hkb = __shfl_sync(0xFFFFFFFFu, hb, k);   // j = k+32
            z2a += hka * sm[S_W2 + k * HID + lane]
                 + hkb * sm[S_W2 + (k + 32) * HID + lane];
            z2b += hka * sm[S_W2 + k * HID + lane + 32]
                 + hkb * sm[S_W2 + (k + 32) * HID + lane + 32];
        }

        // ---- output layer + dz2 (upstream grad = 1) ----
        const float sg2a = fsigmoid(z2a), sg2b = fsigmoid(z2b);
        float epart = z2a * sg2a * w3a + z2b * sg2b * w3b;
        const float dz2a = w3a * (sg2a * (1.0f + z2a * (1.0f - sg2a)));
        const float dz2b = w3b * (sg2b * (1.0f + z2b * (1.0f - sg2b)));

        // ---- backward: dh_j for j = lane, lane+32 via W2T ----
        float dha = 0.0f, dhb = 0.0f;
        #pragma unroll
        for (int k = 0; k < 32; k++) {
            const float da = __shfl_sync(0xFFFFFFFFu, dz2a, k);  // m = k
            const float db = __shfl_sync(0xFFFFFFFFu, dz2b, k);  // m = k+32
            dha += da * sm[S_W2T + k * HID + lane]
                 + db * sm[S_W2T + (k + 32) * HID + lane];
            dhb += da * sm[S_W2T + k * HID + lane + 32]
                 + db * sm[S_W2T + (k + 32) * HID + lane + 32];
        }
        float ddpart = dha * ta + dhb * tb;

        // ---- butterfly reductions ----
        #pragma unroll
        for (int off = 16; off; off >>= 1) {
            epart  += __shfl_xor_sync(0xFFFFFFFFu, epart,  off);
            ddpart += __shfl_xor_sync(0xFFFFFFFFu, ddpart, off);
        }
        if (lane == 0) g_pts[p] = make_float2(epart + b3v, ddpart);
    }
}

// ============================================================================
// Kernel 2: per-edge — dist, table interp, scalar force REDs, e/stress reduce
// ============================================================================
#define ETPB 256
#define EPT  4     // tile = 1024 edges; graphs are 98304-aligned (divisible by 128)

__global__ __launch_bounds__(ETPB)
void edge_kernel(const float* __restrict__ pos, const float* __restrict__ bv,
                 const int* __restrict__ src, const int* __restrict__ dst,
                 const int* __restrict__ eg, int E, int N)
{
    __shared__ float se[NG];
    __shared__ float ss[NG * 9];
    const int tid = threadIdx.x;
    if (tid < NG)     se[tid] = 0.0f;
    if (tid < NG * 9) ss[tid] = 0.0f;
    __syncthreads();

    const int lane = tid & 31;
    const int warp_base = blockIdx.x * (ETPB * EPT) + (tid >> 5) * (32 * EPT);
    // whole warp tile lies in one graph (tiles 128-aligned, graphs 98304-aligned)
    const int g0 = (warp_base < E) ? eg[warp_base] : 0;

    float acc[10];
    #pragma unroll
    for (int q = 0; q < 10; q++) acc[q] = 0.0f;

    #pragma unroll
    for (int k = 0; k < EPT; k++) {
        const int e = warp_base + k * 32 + lane;
        if (e >= E) break;
        const int ns = src[e], nd = dst[e];
        const float bx = bv[3*e+0], by = bv[3*e+1], bz = bv[3*e+2];
        const float dx = bx + pos[3*nd+0] - pos[3*ns+0];
        const float dy = by + pos[3*nd+1] - pos[3*ns+1];
        const float dz = bz + pos[3*nd+2] - pos[3*ns+2];
        const float dist = sqrtf(dx*dx + dy*dy + dz*dz + 1e-12f);

        // table interp (clamp: beyond DMAX the fp32 reference is exactly constant)
        float s = fminf(dist * TBL_INVH, (float)TBL_N - 0.001f);
        const int   ti = (int)s;
        const float fr = s - (float)ti;
        const float2 a = g_pts[ti];
        const float2 b = g_pts[ti + 1];
        const float ee = a.x + fr * (b.x - a.x);
        const float dd = a.y + fr * (b.y - a.y);

        const float sc = __fdividef(dd, dist);
        const float gx = sc * dx, gy = sc * dy, gz = sc * dz;  // gpos contribution

        atomicAdd(&g_scr[8 + 3*nd + 0],  gx);
        atomicAdd(&g_scr[8 + 3*nd + 1],  gy);
        atomicAdd(&g_scr[8 + 3*nd + 2],  gz);
        atomicAdd(&g_scr[8 + 3*ns + 0], -gx);
        atomicAdd(&g_scr[8 + 3*ns + 1], -gy);
        atomicAdd(&g_scr[8 + 3*ns + 2], -gz);

        const float fx = -gx, fy = -gy, fz = -gz;   // f_ij
        acc[0] += ee;
        acc[1] += bx*fx; acc[2] += bx*fy; acc[3] += bx*fz;
        acc[4] += by*fx; acc[5] += by*fy; acc[6] += by*fz;
        acc[7] += bz*fx; acc[8] += bz*fy; acc[9] += bz*fz;
    }

    // warp butterfly (whole warp shares graph g0 by construction)
    #pragma unroll
    for (int off = 16; off; off >>= 1) {
        #pragma unroll
        for (int q = 0; q < 10; q++)
            acc[q] += __shfl_xor_sync(0xFFFFFFFFu, acc[q], off);
    }
    if (lane == 0 && warp_base < E) {
        atomicAdd(&se[g0], acc[0]);
        #pragma unroll
        for (int q = 0; q < 9; q++) atomicAdd(&ss[g0*9 + q], acc[1 + q]);
    }

    __syncthreads();
    if (tid < NG)     atomicAdd(&g_scr[tid], se[tid]);
    if (tid < NG * 9) atomicAdd(&g_scr[8 + 3*N + tid], ss[tid]);
}

// ============================================================================
// Kernel 3: write every out element; re-zero scratch for graph replay
// ============================================================================
__global__ void finalize2(float* __restrict__ out, const float* __restrict__ volume,
                          int N, int out_size) {
    int i = blockIdx.x * blockDim.x + threadIdx.x;
    const int nf = 3 * N;
    if (i < 8) {
        out[i] = g_scr[i];
        g_scr[i] = 0.0f;
    } else if (i < 8 + nf) {
        out[i] = -g_scr[i];                        // forces = -gpos
        g_scr[i] = 0.0f;
    } else if (i < 8 + nf + 72) {
        int s = i - 8 - nf;
        int g = s / 9;
        float vol0 = volume[g * (N / NG)];
        out[i] = (-EV2GPA) * g_scr[i] / vol0;      // scaled stress
        g_scr[i] = 0.0f;
    } else if (i < out_size) {
        out[i] = 0.0f;                             // hessian
    }
}

extern "C" void kernel_launch(void* const* d_in, const int* in_sizes, int n_in,
                              void* d_out, int out_size) {
    const float* pos     = (const float*)d_in[0];
    const float* bv      = (const float*)d_in[1];
    const int*   src     = (const int*)  d_in[2];
    const int*   dst     = (const int*)  d_in[3];
    const int*   eg      = (const int*)  d_in[4];
    const float* volume  = (const float*)d_in[5];
    const float* centers = (const float*)d_in[6];
    const float* W1      = (const float*)d_in[7];
    const float* b1      = (const float*)d_in[8];
    const float* W2      = (const float*)d_in[9];
    const float* b2      = (const float*)d_in[10];
    const float* W3      = (const float*)d_in[11];
    const float* b3      = (const float*)d_in[12];
    float* out = (float*)d_out;

    const int N = in_sizes[0] / 3;
    const int E = in_sizes[1] / 3;

    build_pts_kernel<<<BGRID, BTPB>>>(W1, b1, W2, b2, W3, b3, centers);
    edge_kernel<<<(E + ETPB * EPT - 1) / (ETPB * EPT), ETPB>>>(pos, bv, src, dst, eg, E, N);
    finalize2<<<(out_size + 255) / 256, 256>>>(out, volume, N, out_size);
}

// round 10
// speedup vs baseline: 1.0829x; 1.0829x over previous
#include <cuda_runtime.h>
#include <math.h>

#define RBF_K 32
#define HID   64
#define NG    8
#define NMAX  49152
#define EV2GPA 160.21766208f

#define TBL_N    16384
#define TBL_DMAX 16.0f
#define TBL_INVH ((float)TBL_N / TBL_DMAX)

// persistent device scratch (static — no runtime allocation)
__device__ float  g_scr[8 + 3 * NMAX + 72];   // [0:8) energy, [8:8+3N) gpos, then raw stress
__device__ float2 g_pts[TBL_N + 1];           // (e, dd) samples

__device__ __forceinline__ float fsigmoid(float z) {
    return __fdividef(1.0f, 1.0f + __expf(-z));
}

// ============================================================================
// Kernel 1: warp-per-4-points table build (weight LDS amortized over 4 points)
//   lane = rbf index k for the exp stage
//   lane = hidden pair (j, j+32) for layer 1 / (m, m+32) for layer 2
// ============================================================================
#define BTPB   512
#define BGRID  296
#define NP     4
// smem (floats): W1[K][H] row-major, W2[H][H], W2T[m][j], b1, b2, w3
#define S_W1  0
#define S_W2  (S_W1 + RBF_K*HID)
#define S_W2T (S_W2 + HID*HID)
#define S_B1  (S_W2T + HID*HID)
#define S_B2  (S_B1 + HID)
#define S_W3  (S_B2 + HID)
#define S_TOT (S_W3 + HID)

__global__ __launch_bounds__(BTPB, 1)
void build_pts_kernel(const float* __restrict__ W1, const float* __restrict__ b1,
                      const float* __restrict__ W2, const float* __restrict__ b2,
                      const float* __restrict__ W3, const float* __restrict__ b3,
                      const float* __restrict__ centers)
{
    __shared__ float sm[S_TOT];
    const int tid = threadIdx.x;
    for (int i = tid; i < RBF_K * HID; i += BTPB) sm[S_W1 + i] = W1[i];
    for (int i = tid; i < HID * HID; i += BTPB) {
        float w = W2[i];
        sm[S_W2 + i] = w;
        const int j = i >> 6, m = i & 63;
        sm[S_W2T + m * HID + j] = w;              // transpose for backward
    }
    if (tid < HID) {
        sm[S_B1 + tid] = b1[tid];
        sm[S_B2 + tid] = b2[tid];
        sm[S_W3 + tid] = W3[tid];
    }
    __syncthreads();

    const int lane = tid & 31;
    const int gwarp = (blockIdx.x * BTPB + tid) >> 5;

    const float cme = centers[lane];              // center for k = lane
    const float b3v = b3[0];
    const float b1a = sm[S_B1 + lane], b1b = sm[S_B1 + lane + 32];
    const float b2a = sm[S_B2 + lane], b2b = sm[S_B2 + lane + 32];
    const float w3a = sm[S_W3 + lane], w3b = sm[S_W3 + lane + 32];

    const int p0 = gwarp * NP;                    // 4736 warps * 4 = 18944 >= 16385
    if (p0 > TBL_N) return;

    // per-point state
    float r[NP], dr[NP];
    #pragma unroll
    for (int q = 0; q < NP; q++) {
        const float d = (float)(p0 + q) * (TBL_DMAX / (float)TBL_N);
        const float t = d - cme;
        r[q]  = __expf(-t * t);
        dr[q] = -2.0f * t * r[q];
    }

    // ---- layer 1: z1_j, u_j for j = lane, lane+32, all NP points ----
    float z1a[NP], z1b[NP], ua[NP], ub[NP];
    #pragma unroll
    for (int q = 0; q < NP; q++) { z1a[q] = b1a; z1b[q] = b1b; ua[q] = 0.f; ub[q] = 0.f; }
    #pragma unroll
    for (int k = 0; k < 32; k++) {
        const float wa = sm[S_W1 + k * HID + lane];
        const float wb = sm[S_W1 + k * HID + lane + 32];
        #pragma unroll
        for (int q = 0; q < NP; q++) {
            const float rk  = __shfl_sync(0xFFFFFFFFu, r[q],  k);
            const float drk = __shfl_sync(0xFFFFFFFFu, dr[q], k);
            z1a[q] += rk * wa;   z1b[q] += rk * wb;
            ua[q]  += drk * wa;  ub[q]  += drk * wb;
        }
    }

    // activations; reuse r/dr registers for h; t-values into ua/ub
    float ha[NP], hb[NP];
    #pragma unroll
    for (int q = 0; q < NP; q++) {
        const float sga = fsigmoid(z1a[q]), sgb = fsigmoid(z1b[q]);
        ha[q] = z1a[q] * sga;
        hb[q] = z1b[q] * sgb;
        ua[q] = (sga * (1.0f + z1a[q] * (1.0f - sga))) * ua[q];   // t_j  = silu'*u
        ub[q] = (sgb * (1.0f + z1b[q] * (1.0f - sgb))) * ub[q];
    }

    // ---- layer 2: z2_m for m = lane, lane+32 (reuse z1 regs as z2) ----
    #pragma unroll
    for (int q = 0; q < NP; q++) { z1a[q] = b2a; z1b[q] = b2b; }
    #pragma unroll
    for (int k = 0; k < 32; k++) {
        const float w0a = sm[S_W2 + k * HID + lane];
        const float w0b = sm[S_W2 + (k + 32) * HID + lane];
        const float w1a = sm[S_W2 + k * HID + lane + 32];
        const float w1b = sm[S_W2 + (k + 32) * HID + lane + 32];
        #pragma unroll
        for (int q = 0; q < NP; q++) {
            const float hka = __shfl_sync(0xFFFFFFFFu, ha[q], k);   // j = k
            const float hkb = __shfl_sync(0xFFFFFFFFu, hb[q], k);   // j = k+32
            z1a[q] += hka * w0a + hkb * w0b;
            z1b[q] += hka * w1a + hkb * w1b;
        }
    }

    // ---- output layer + dz2 (upstream grad = 1); reuse r/dr as dz2 ----
    float ep[NP];
    #pragma unroll
    for (int q = 0; q < NP; q++) {
        const float sg2a = fsigmoid(z1a[q]), sg2b = fsigmoid(z1b[q]);
        ep[q] = z1a[q] * sg2a * w3a + z1b[q] * sg2b * w3b;
        r[q]  = w3a * (sg2a * (1.0f + z1a[q] * (1.0f - sg2a)));   // dz2 (m=lane)
        dr[q] = w3b * (sg2b * (1.0f + z1b[q] * (1.0f - sg2b)));   // dz2 (m=lane+32)
    }

    // ---- backward: dh_j via W2T (reuse z1 regs as dh) ----
    #pragma unroll
    for (int q = 0; q < NP; q++) { z1a[q] = 0.f; z1b[q] = 0.f; }
    #pragma unroll
    for (int k = 0; k < 32; k++) {
        const float w0a = sm[S_W2T + k * HID + lane];
        const float w0b = sm[S_W2T + (k + 32) * HID + lane];
        const float w1a = sm[S_W2T + k * HID + lane + 32];
        const float w1b = sm[S_W2T + (k + 32) * HID + lane + 32];
        #pragma unroll
        for (int q = 0; q < NP; q++) {
            const float da = __shfl_sync(0xFFFFFFFFu, r[q],  k);   // m = k
            const float db = __shfl_sync(0xFFFFFFFFu, dr[q], k);   // m = k+32
            z1a[q] += da * w0a + db * w0b;
            z1b[q] += da * w1a + db * w1b;
        }
    }

    float dp[NP];
    #pragma unroll
    for (int q = 0; q < NP; q++) dp[q] = z1a[q] * ua[q] + z1b[q] * ub[q];

    // ---- butterfly reductions (NP points together) ----
    #pragma unroll
    for (int off = 16; off; off >>= 1) {
        #pragma unroll
        for (int q = 0; q < NP; q++) {
            ep[q] += __shfl_xor_sync(0xFFFFFFFFu, ep[q], off);
            dp[q] += __shfl_xor_sync(0xFFFFFFFFu, dp[q], off);
        }
    }
    if (lane == 0) {
        #pragma unroll
        for (int q = 0; q < NP; q++)
            if (p0 + q <= TBL_N) g_pts[p0 + q] = make_float2(ep[q] + b3v, dp[q]);
    }
}

// ============================================================================
// Kernel 2: per-edge — dist, table interp, scalar force REDs, e/stress reduce
// ============================================================================
#define ETPB 256
#define EPT  4     // tile = 1024 edges; graphs are 98304-aligned (divisible by 128)

__global__ __launch_bounds__(ETPB)
void edge_kernel(const float* __restrict__ pos, const float* __restrict__ bv,
                 const int* __restrict__ src, const int* __restrict__ dst,
                 const int* __restrict__ eg, int E, int N)
{
    __shared__ float se[NG];
    __shared__ float ss[NG * 9];
    const int tid = threadIdx.x;
    if (tid < NG)     se[tid] = 0.0f;
    if (tid < NG * 9) ss[tid] = 0.0f;
    __syncthreads();

    const int lane = tid & 31;
    const int warp_base = blockIdx.x * (ETPB * EPT) + (tid >> 5) * (32 * EPT);
    // whole warp tile lies in one graph (tiles 128-aligned, graphs 98304-aligned)
    const int g0 = (warp_base < E) ? eg[warp_base] : 0;

    float acc[10];
    #pragma unroll
    for (int q = 0; q < 10; q++) acc[q] = 0.0f;

    #pragma unroll
    for (int k = 0; k < EPT; k++) {
        const int e = warp_base + k * 32 + lane;
        if (e >= E) break;
        const int ns = src[e], nd = dst[e];
        const float bx = bv[3*e+0], by = bv[3*e+1], bz = bv[3*e+2];
        const float dx = bx + pos[3*nd+0] - pos[3*ns+0];
        const float dy = by + pos[3*nd+1] - pos[3*ns+1];
        const float dz = bz + pos[3*nd+2] - pos[3*ns+2];
        const float dist = sqrtf(dx*dx + dy*dy + dz*dz + 1e-12f);

        // table interp (clamp: beyond DMAX the fp32 reference is exactly constant)
        float s = fminf(dist * TBL_INVH, (float)TBL_N - 0.001f);
        const int   ti = (int)s;
        const float fr = s - (float)ti;
        const float2 a = g_pts[ti];
        const float2 b = g_pts[ti + 1];
        const float ee = a.x + fr * (b.x - a.x);
        const float dd = a.y + fr * (b.y - a.y);

        const float sc = __fdividef(dd, dist);
        const float gx = sc * dx, gy = sc * dy, gz = sc * dz;  // gpos contribution

        atomicAdd(&g_scr[8 + 3*nd + 0],  gx);
        atomicAdd(&g_scr[8 + 3*nd + 1],  gy);
        atomicAdd(&g_scr[8 + 3*nd + 2],  gz);
        atomicAdd(&g_scr[8 + 3*ns + 0], -gx);
        atomicAdd(&g_scr[8 + 3*ns + 1], -gy);
        atomicAdd(&g_scr[8 + 3*ns + 2], -gz);

        const float fx = -gx, fy = -gy, fz = -gz;   // f_ij
        acc[0] += ee;
        acc[1] += bx*fx; acc[2] += bx*fy; acc[3] += bx*fz;
        acc[4] += by*fx; acc[5] += by*fy; acc[6] += by*fz;
        acc[7] += bz*fx; acc[8] += bz*fy; acc[9] += bz*fz;
    }

    // warp butterfly (whole warp shares graph g0 by construction)
    #pragma unroll
    for (int off = 16; off; off >>= 1) {
        #pragma unroll
        for (int q = 0; q < 10; q++)
            acc[q] += __shfl_xor_sync(0xFFFFFFFFu, acc[q], off);
    }
    if (lane == 0 && warp_base < E) {
        atomicAdd(&se[g0], acc[0]);
        #pragma unroll
        for (int q = 0; q < 9; q++) atomicAdd(&ss[g0*9 + q], acc[1 + q]);
    }

    __syncthreads();
    if (tid < NG)     atomicAdd(&g_scr[tid], se[tid]);
    if (tid < NG * 9) atomicAdd(&g_scr[8 + 3*N + tid], ss[tid]);
}

// ============================================================================
// Kernel 3: write every out element; re-zero scratch for graph replay
// ============================================================================
__global__ void finalize2(float* __restrict__ out, const float* __restrict__ volume,
                          int N, int out_size) {
    int i = blockIdx.x * blockDim.x + threadIdx.x;
    const int nf = 3 * N;
    if (i < 8) {
        out[i] = g_scr[i];
        g_scr[i] = 0.0f;
    } else if (i < 8 + nf) {
        out[i] = -g_scr[i];                        // forces = -gpos
        g_scr[i] = 0.0f;
    } else if (i < 8 + nf + 72) {
        int s = i - 8 - nf;
        int g = s / 9;
        float vol0 = volume[g * (N / NG)];
        out[i] = (-EV2GPA) * g_scr[i] / vol0;      // scaled stress
        g_scr[i] = 0.0f;
    } else if (i < out_size) {
        out[i] = 0.0f;                             // hessian
    }
}

extern "C" void kernel_launch(void* const* d_in, const int* in_sizes, int n_in,
                              void* d_out, int out_size) {
    const float* pos     = (const float*)d_in[0];
    const float* bv      = (const float*)d_in[1];
    const int*   src     = (const int*)  d_in[2];
    const int*   dst     = (const int*)  d_in[3];
    const int*   eg      = (const int*)  d_in[4];
    const float* volume  = (const float*)d_in[5];
    const float* centers = (const float*)d_in[6];
    const float* W1      = (const float*)d_in[7];
    const float* b1      = (const float*)d_in[8];
    const float* W2      = (const float*)d_in[9];
    const float* b2      = (const float*)d_in[10];
    const float* W3      = (const float*)d_in[11];
    const float* b3      = (const float*)d_in[12];
    float* out = (float*)d_out;

    const int N = in_sizes[0] / 3;
    const int E = in_sizes[1] / 3;

    build_pts_kernel<<<BGRID, BTPB>>>(W1, b1, W2, b2, W3, b3, centers);
    edge_kernel<<<(E + ETPB * EPT - 1) / (ETPB * EPT), ETPB>>>(pos, bv, src, dst, eg, E, N);
    finalize2<<<(out_size + 255) / 256, 256>>>(out, volume, N, out_size);
}

// round 12
// speedup vs baseline: 1.4091x; 1.3012x over previous
#include <cuda_runtime.h>
#include <math.h>

#define RBF_K 32
#define HID   64
#define NG    8
#define NMAX  49152
#define EV2GPA 160.21766208f

#define TBL_N    8192
#define TBL_DMAX 16.0f
#define TBL_INVH ((float)TBL_N / TBL_DMAX)

// persistent device scratch (static — no runtime allocation)
__device__ float  g_scr[8 + 3 * NMAX + 72];   // [0:8) energy, [8:8+3N) gpos, then raw stress
__device__ float4 g_table[TBL_N];             // (e_i, dd_i, e_{i+1}-e_i, dd_{i+1}-dd_i)

__device__ __forceinline__ float fsigmoid(float z) {
    return __fdividef(1.0f, 1.0f + __expf(-z));
}

// ============================================================================
// Kernel 1: warp-per-5-points table build; writes 4 packed float4 entries.
//   lane = rbf index k for the exp stage
//   lane = hidden pair (j, j+32) for layer 1 / (m, m+32) for layer 2
// ============================================================================
#define BTPB   512
#define BGRID  128           // 128*16 = 2048 warps * 4 entries = 8192 = TBL_N
#define NP     5             // points per warp (4 entries + 1 overlap)
// smem (floats): W1[K][H] row-major, W2[H][H], W2T[m][j], b1, b2, w3
#define S_W1  0
#define S_W2  (S_W1 + RBF_K*HID)
#define S_W2T (S_W2 + HID*HID)
#define S_B1  (S_W2T + HID*HID)
#define S_B2  (S_B1 + HID)
#define S_W3  (S_B2 + HID)
#define S_TOT (S_W3 + HID)

__global__ __launch_bounds__(BTPB, 1)
void build_pts_kernel(const float* __restrict__ W1, const float* __restrict__ b1,
                      const float* __restrict__ W2, const float* __restrict__ b2,
                      const float* __restrict__ W3, const float* __restrict__ b3,
                      const float* __restrict__ centers)
{
    __shared__ float sm[S_TOT];
    const int tid = threadIdx.x;
    for (int i = tid; i < RBF_K * HID; i += BTPB) sm[S_W1 + i] = W1[i];
    for (int i = tid; i < HID * HID; i += BTPB) {
        float w = W2[i];
        sm[S_W2 + i] = w;
        const int j = i >> 6, m = i & 63;
        sm[S_W2T + m * HID + j] = w;              // transpose for backward
    }
    if (tid < HID) {
        sm[S_B1 + tid] = b1[tid];
        sm[S_B2 + tid] = b2[tid];
        sm[S_W3 + tid] = W3[tid];
    }
    __syncthreads();

    const int lane = tid & 31;
    const int gwarp = (blockIdx.x * BTPB + tid) >> 5;
    const int p0 = gwarp * (NP - 1);              // entries p0..p0+3; points p0..p0+4
    if (p0 >= TBL_N) return;

    const float cme = centers[lane];              // center for k = lane
    const float b3v = b3[0];
    const float b1a = sm[S_B1 + lane], b1b = sm[S_B1 + lane + 32];
    const float b2a = sm[S_B2 + lane], b2b = sm[S_B2 + lane + 32];
    const float w3a = sm[S_W3 + lane], w3b = sm[S_W3 + lane + 32];

    // per-point state
    float r[NP], dr[NP];
    #pragma unroll
    for (int q = 0; q < NP; q++) {
        const float d = (float)(p0 + q) * (TBL_DMAX / (float)TBL_N);
        const float t = d - cme;
        r[q]  = __expf(-t * t);
        dr[q] = -2.0f * t * r[q];
    }

    // ---- layer 1: z1_j, u_j for j = lane, lane+32, all NP points ----
    float z1a[NP], z1b[NP], ua[NP], ub[NP];
    #pragma unroll
    for (int q = 0; q < NP; q++) { z1a[q] = b1a; z1b[q] = b1b; ua[q] = 0.f; ub[q] = 0.f; }
    #pragma unroll
    for (int k = 0; k < 32; k++) {
        const float wa = sm[S_W1 + k * HID + lane];
        const float wb = sm[S_W1 + k * HID + lane + 32];
        #pragma unroll
        for (int q = 0; q < NP; q++) {
            const float rk  = __shfl_sync(0xFFFFFFFFu, r[q],  k);
            const float drk = __shfl_sync(0xFFFFFFFFu, dr[q], k);
            z1a[q] += rk * wa;   z1b[q] += rk * wb;
            ua[q]  += drk * wa;  ub[q]  += drk * wb;
        }
    }

    // activations; t-values overwrite ua/ub; h into ha/hb
    float ha[NP], hb[NP];
    #pragma unroll
    for (int q = 0; q < NP; q++) {
        const float sga = fsigmoid(z1a[q]), sgb = fsigmoid(z1b[q]);
        ha[q] = z1a[q] * sga;
        hb[q] = z1b[q] * sgb;
        ua[q] = (sga * (1.0f + z1a[q] * (1.0f - sga))) * ua[q];   // t_j = silu'*u
        ub[q] = (sgb * (1.0f + z1b[q] * (1.0f - sgb))) * ub[q];
    }

    // ---- layer 2: z2_m for m = lane, lane+32 (reuse z1 regs as z2) ----
    #pragma unroll
    for (int q = 0; q < NP; q++) { z1a[q] = b2a; z1b[q] = b2b; }
    #pragma unroll
    for (int k = 0; k < 32; k++) {
        const float w0a = sm[S_W2 + k * HID + lane];
        const float w0b = sm[S_W2 + (k + 32) * HID + lane];
        const float w1a = sm[S_W2 + k * HID + lane + 32];
        const float w1b = sm[S_W2 + (k + 32) * HID + lane + 32];
        #pragma unroll
        for (int q = 0; q < NP; q++) {
            const float hka = __shfl_sync(0xFFFFFFFFu, ha[q], k);   // j = k
            const float hkb = __shfl_sync(0xFFFFFFFFu, hb[q], k);   // j = k+32
            z1a[q] += hka * w0a + hkb * w0b;
            z1b[q] += hka * w1a + hkb * w1b;
        }
    }

    // ---- output layer + dz2 (upstream grad = 1); reuse r/dr as dz2 ----
    float ep[NP];
    #pragma unroll
    for (int q = 0; q < NP; q++) {
        const float sg2a = fsigmoid(z1a[q]), sg2b = fsigmoid(z1b[q]);
        ep[q] = z1a[q] * sg2a * w3a + z1b[q] * sg2b * w3b;
        r[q]  = w3a * (sg2a * (1.0f + z1a[q] * (1.0f - sg2a)));   // dz2 (m=lane)
        dr[q] = w3b * (sg2b * (1.0f + z1b[q] * (1.0f - sg2b)));   // dz2 (m=lane+32)
    }

    // ---- backward: dh_j via W2T (reuse z1 regs as dh) ----
    #pragma unroll
    for (int q = 0; q < NP; q++) { z1a[q] = 0.f; z1b[q] = 0.f; }
    #pragma unroll
    for (int k = 0; k < 32; k++) {
        const float w0a = sm[S_W2T + k * HID + lane];
        const float w0b = sm[S_W2T + (k + 32) * HID + lane];
        const float w1a = sm[S_W2T + k * HID + lane + 32];
        const float w1b = sm[S_W2T + (k + 32) * HID + lane + 32];
        #pragma unroll
        for (int q = 0; q < NP; q++) {
            const float da = __shfl_sync(0xFFFFFFFFu, r[q],  k);   // m = k
            const float db = __shfl_sync(0xFFFFFFFFu, dr[q], k);   // m = k+32
            z1a[q] += da * w0a + db * w0b;
            z1b[q] += da * w1a + db * w1b;
        }
    }

    float dp[NP];
    #pragma unroll
    for (int q = 0; q < NP; q++) dp[q] = z1a[q] * ua[q] + z1b[q] * ub[q];

    // ---- butterfly reductions ----
    #pragma unroll
    for (int off = 16; off; off >>= 1) {
        #pragma unroll
        for (int q = 0; q < NP; q++) {
            ep[q] += __shfl_xor_sync(0xFFFFFFFFu, ep[q], off);
            dp[q] += __shfl_xor_sync(0xFFFFFFFFu, dp[q], off);
        }
    }
    // lane 0 writes 4 packed entries (b3 offsets cancel in the slopes)
    if (lane == 0) {
        #pragma unroll
        for (int q = 0; q < NP - 1; q++)
            g_table[p0 + q] = make_float4(ep[q] + b3v, dp[q],
                                          ep[q + 1] - ep[q], dp[q + 1] - dp[q]);
    }
}

// ============================================================================
// Kernel 2: per-edge — dist, float4 table interp, scalar REDs, e/stress reduce
// ============================================================================
#define ETPB 256
#define EPT  4     // tile = 1024 edges; graphs are 98304-aligned (divisible by 128)

__global__ __launch_bounds__(ETPB)
void edge_kernel(const float* __restrict__ pos, const float* __restrict__ bv,
                 const int* __restrict__ src, const int* __restrict__ dst,
                 const int* __restrict__ eg, int E, int N)
{
    __shared__ float se[NG];
    __shared__ float ss[NG * 9];
    const int tid = threadIdx.x;
    if (tid < NG)     se[tid] = 0.0f;
    if (tid < NG * 9) ss[tid] = 0.0f;
    __syncthreads();

    const int lane = tid & 31;
    const int warp_base = blockIdx.x * (ETPB * EPT) + (tid >> 5) * (32 * EPT);
    // whole warp tile lies in one graph (tiles 128-aligned, graphs 98304-aligned)
    const int g0 = (warp_base < E) ? eg[warp_base] : 0;
    const bool full = (warp_base + 32 * EPT) <= E;

    float acc[10];
    #pragma unroll
    for (int q = 0; q < 10; q++) acc[q] = 0.0f;

    #pragma unroll
    for (int k = 0; k < EPT; k++) {
        const int e = warp_base + k * 32 + lane;
        if (!full && e >= E) break;
        const int ns = src[e], nd = dst[e];
        const float bx = bv[3*e+0], by = bv[3*e+1], bz = bv[3*e+2];
        const float dx = bx + pos[3*nd+0] - pos[3*ns+0];
        const float dy = by + pos[3*nd+1] - pos[3*ns+1];
        const float dz = bz + pos[3*nd+2] - pos[3*ns+2];
        const float dist = sqrtf(dx*dx + dy*dy + dz*dz + 1e-12f);

        // table interp (clamp: beyond DMAX the fp32 reference is exactly constant)
        float s = fminf(dist * TBL_INVH, (float)TBL_N - 0.001f);
        const int   ti = (int)s;
        const float fr = s - (float)ti;
        const float4 tb = g_table[ti];
        const float ee = tb.x + fr * tb.z;
        const float dd = tb.y + fr * tb.w;

        const float sc = __fdividef(dd, dist);
        const float gx = sc * dx, gy = sc * dy, gz = sc * dz;  // gpos contribution

        atomicAdd(&g_scr[8 + 3*nd + 0],  gx);
        atomicAdd(&g_scr[8 + 3*nd + 1],  gy);
        atomicAdd(&g_scr[8 + 3*nd + 2],  gz);
        atomicAdd(&g_scr[8 + 3*ns + 0], -gx);
        atomicAdd(&g_scr[8 + 3*ns + 1], -gy);
        atomicAdd(&g_scr[8 + 3*ns + 2], -gz);

        const float fx = -gx, fy = -gy, fz = -gz;   // f_ij
        acc[0] += ee;
        acc[1] += bx*fx; acc[2] += bx*fy; acc[3] += bx*fz;
        acc[4] += by*fx; acc[5] += by*fy; acc[6] += by*fz;
        acc[7] += bz*fx; acc[8] += bz*fy; acc[9] += bz*fz;
    }

    // warp butterfly (whole warp shares graph g0 by construction)
    #pragma unroll
    for (int off = 16; off; off >>= 1) {
        #pragma unroll
        for (int q = 0; q < 10; q++)
            acc[q] += __shfl_xor_sync(0xFFFFFFFFu, acc[q], off);
    }
    if (lane == 0 && warp_base < E) {
        atomicAdd(&se[g0], acc[0]);
        #pragma unroll
        for (int q = 0; q < 9; q++) atomicAdd(&ss[g0*9 + q], acc[1 + q]);
    }

    __syncthreads();
    if (tid < NG)     atomicAdd(&g_scr[tid], se[tid]);
    if (tid < NG * 9) atomicAdd(&g_scr[8 + 3*N + tid], ss[tid]);
}

// ============================================================================
// Kernel 3: write every out element; re-zero scratch for graph replay
// ============================================================================
__global__ void finalize2(float* __restrict__ out, const float* __restrict__ volume,
                          int N, int out_size) {
    int i = blockIdx.x * blockDim.x + threadIdx.x;
    const int nf = 3 * N;
    if (i < 8) {
        out[i] = g_scr[i];
        g_scr[i] = 0.0f;
    } else if (i < 8 + nf) {
        out[i] = -g_scr[i];                        // forces = -gpos
        g_scr[i] = 0.0f;
    } else if (i < 8 + nf + 72) {
        int s = i - 8 - nf;
        int g = s / 9;
        float vol0 = volume[g * (N / NG)];
        out[i] = (-EV2GPA) * g_scr[i] / vol0;      // scaled stress
        g_scr[i] = 0.0f;
    } else if (i < out_size) {
        out[i] = 0.0f;                             // hessian
    }
}

extern "C" void kernel_launch(void* const* d_in, const int* in_sizes, int n_in,
                              void* d_out, int out_size) {
    const float* pos     = (const float*)d_in[0];
    const float* bv      = (const float*)d_in[1];
    const int*   src     = (const int*)  d_in[2];
    const int*   dst     = (const int*)  d_in[3];
    const int*   eg      = (const int*)  d_in[4];
    const float* volume  = (const float*)d_in[5];
    const float* centers = (const float*)d_in[6];
    const float* W1      = (const float*)d_in[7];
    const float* b1      = (const float*)d_in[8];
    const float* W2      = (const float*)d_in[9];
    const float* b2      = (const float*)d_in[10];
    const float* W3      = (const float*)d_in[11];
    const float* b3      = (const float*)d_in[12];
    float* out = (float*)d_out;

    const int N = in_sizes[0] / 3;
    const int E = in_sizes[1] / 3;

    build_pts_kernel<<<BGRID, BTPB>>>(W1, b1, W2, b2, W3, b3, centers);
    edge_kernel<<<(E + ETPB * EPT - 1) / (ETPB * EPT), ETPB>>>(pos, bv, src, dst, eg, E, N);
    finalize2<<<(out_size + 255) / 256, 256>>>(out, volume, N, out_size);
}

// round 13
// speedup vs baseline: 1.5207x; 1.0793x over previous
#include <cuda_runtime.h>
#include <math.h>

#define RBF_K 32
#define HID   64
#define NG    8
#define NMAX  49152
#define EV2GPA 160.21766208f

#define TBL_N    4096
#define TBL_DMAX 16.0f
#define TBL_INVH ((float)TBL_N / TBL_DMAX)

// persistent device scratch (static — no runtime allocation)
__device__ float  g_scr[8 + 3 * NMAX + 72];   // [0:8) energy, [8:8+3N) gpos, then raw stress
__device__ float4 g_table[TBL_N];             // (e_i, dd_i, e_{i+1}-e_i, dd_{i+1}-dd_i)
__device__ float4 g_posw[NMAX];               // padded positions (w unused)

__device__ __forceinline__ float fsigmoid(float z) {
    return __fdividef(1.0f, 1.0f + __expf(-z));
}

// ============================================================================
// Kernel 0: pad pos[N,3] -> float4 so edge gathers are single LDG.128
// ============================================================================
__global__ void pad_pos_kernel(const float* __restrict__ pos, int N) {
    int n = blockIdx.x * blockDim.x + threadIdx.x;
    if (n < N)
        g_posw[n] = make_float4(pos[3*n+0], pos[3*n+1], pos[3*n+2], 0.0f);
}

// ============================================================================
// Kernel 1: warp-per-3-points table build; writes 2 packed float4 entries.
//   lane = rbf index k for the exp stage
//   lane = hidden pair (j, j+32) for layer 1 / (m, m+32) for layer 2
// ============================================================================
#define BTPB   512
#define BGRID  128           // 128*16 = 2048 warps * 2 entries = 4096 = TBL_N
#define NP     3             // points per warp (2 entries + 1 overlap)
// smem (floats): W1[K][H] row-major, W2[H][H], W2T[m][j], b1, b2, w3
#define S_W1  0
#define S_W2  (S_W1 + RBF_K*HID)
#define S_W2T (S_W2 + HID*HID)
#define S_B1  (S_W2T + HID*HID)
#define S_B2  (S_B1 + HID)
#define S_W3  (S_B2 + HID)
#define S_TOT (S_W3 + HID)

__global__ __launch_bounds__(BTPB, 1)
void build_pts_kernel(const float* __restrict__ W1, const float* __restrict__ b1,
                      const float* __restrict__ W2, const float* __restrict__ b2,
                      const float* __restrict__ W3, const float* __restrict__ b3,
                      const float* __restrict__ centers)
{
    __shared__ float sm[S_TOT];
    const int tid = threadIdx.x;
    for (int i = tid; i < RBF_K * HID; i += BTPB) sm[S_W1 + i] = W1[i];
    for (int i = tid; i < HID * HID; i += BTPB) {
        float w = W2[i];
        sm[S_W2 + i] = w;
        const int j = i >> 6, m = i & 63;
        sm[S_W2T + m * HID + j] = w;              // transpose for backward
    }
    if (tid < HID) {
        sm[S_B1 + tid] = b1[tid];
        sm[S_B2 + tid] = b2[tid];
        sm[S_W3 + tid] = W3[tid];
    }
    __syncthreads();

    const int lane = tid & 31;
    const int gwarp = (blockIdx.x * BTPB + tid) >> 5;
    const int p0 = gwarp * (NP - 1);              // entries p0, p0+1; points p0..p0+2
    if (p0 >= TBL_N) return;

    const float cme = centers[lane];              // center for k = lane
    const float b3v = b3[0];
    const float b1a = sm[S_B1 + lane], b1b = sm[S_B1 + lane + 32];
    const float b2a = sm[S_B2 + lane], b2b = sm[S_B2 + lane + 32];
    const float w3a = sm[S_W3 + lane], w3b = sm[S_W3 + lane + 32];

    // per-point state
    float r[NP], dr[NP];
    #pragma unroll
    for (int q = 0; q < NP; q++) {
        const float d = (float)(p0 + q) * (TBL_DMAX / (float)TBL_N);
        const float t = d - cme;
        r[q]  = __expf(-t * t);
        dr[q] = -2.0f * t * r[q];
    }

    // ---- layer 1: z1_j, u_j for j = lane, lane+32, all NP points ----
    float z1a[NP], z1b[NP], ua[NP], ub[NP];
    #pragma unroll
    for (int q = 0; q < NP; q++) { z1a[q] = b1a; z1b[q] = b1b; ua[q] = 0.f; ub[q] = 0.f; }
    #pragma unroll
    for (int k = 0; k < 32; k++) {
        const float wa = sm[S_W1 + k * HID + lane];
        const float wb = sm[S_W1 + k * HID + lane + 32];
        #pragma unroll
        for (int q = 0; q < NP; q++) {
            const float rk  = __shfl_sync(0xFFFFFFFFu, r[q],  k);
            const float drk = __shfl_sync(0xFFFFFFFFu, dr[q], k);
            z1a[q] += rk * wa;   z1b[q] += rk * wb;
            ua[q]  += drk * wa;  ub[q]  += drk * wb;
        }
    }

    // activations; t-values overwrite ua/ub; h into ha/hb
    float ha[NP], hb[NP];
    #pragma unroll
    for (int q = 0; q < NP; q++) {
        const float sga = fsigmoid(z1a[q]), sgb = fsigmoid(z1b[q]);
        ha[q] = z1a[q] * sga;
        hb[q] = z1b[q] * sgb;
        ua[q] = (sga * (1.0f + z1a[q] * (1.0f - sga))) * ua[q];   // t_j = silu'*u
        ub[q] = (sgb * (1.0f + z1b[q] * (1.0f - sgb))) * ub[q];
    }

    // ---- layer 2: z2_m for m = lane, lane+32 (reuse z1 regs as z2) ----
    #pragma unroll
    for (int q = 0; q < NP; q++) { z1a[q] = b2a; z1b[q] = b2b; }
    #pragma unroll
    for (int k = 0; k < 32; k++) {
        const float w0a = sm[S_W2 + k * HID + lane];
        const float w0b = sm[S_W2 + (k + 32) * HID + lane];
        const float w1a = sm[S_W2 + k * HID + lane + 32];
        const float w1b = sm[S_W2 + (k + 32) * HID + lane + 32];
        #pragma unroll
        for (int q = 0; q < NP; q++) {
            const float hka = __shfl_sync(0xFFFFFFFFu, ha[q], k);   // j = k
            const float hkb = __shfl_sync(0xFFFFFFFFu, hb[q], k);   // j = k+32
            z1a[q] += hka * w0a + hkb * w0b;
            z1b[q] += hka * w1a + hkb * w1b;
        }
    }

    // ---- output layer + dz2 (upstream grad = 1); reuse r/dr as dz2 ----
    float ep[NP];
    #pragma unroll
    for (int q = 0; q < NP; q++) {
        const float sg2a = fsigmoid(z1a[q]), sg2b = fsigmoid(z1b[q]);
        ep[q] = z1a[q] * sg2a * w3a + z1b[q] * sg2b * w3b;
        r[q]  = w3a * (sg2a * (1.0f + z1a[q] * (1.0f - sg2a)));   // dz2 (m=lane)
        dr[q] = w3b * (sg2b * (1.0f + z1b[q] * (1.0f - sg2b)));   // dz2 (m=lane+32)
    }

    // ---- backward: dh_j via W2T (reuse z1 regs as dh) ----
    #pragma unroll
    for (int q = 0; q < NP; q++) { z1a[q] = 0.f; z1b[q] = 0.f; }
    #pragma unroll
    for (int k = 0; k < 32; k++) {
        const float w0a = sm[S_W2T + k * HID + lane];
        const float w0b = sm[S_W2T + (k + 32) * HID + lane];
        const float w1a = sm[S_W2T + k * HID + lane + 32];
        const float w1b = sm[S_W2T + (k + 32) * HID + lane + 32];
        #pragma unroll
        for (int q = 0; q < NP; q++) {
            const float da = __shfl_sync(0xFFFFFFFFu, r[q],  k);   // m = k
            const float db = __shfl_sync(0xFFFFFFFFu, dr[q], k);   // m = k+32
            z1a[q] += da * w0a + db * w0b;
            z1b[q] += da * w1a + db * w1b;
        }
    }

    float dp[NP];
    #pragma unroll
    for (int q = 0; q < NP; q++) dp[q] = z1a[q] * ua[q] + z1b[q] * ub[q];

    // ---- butterfly reductions ----
    #pragma unroll
    for (int off = 16; off; off >>= 1) {
        #pragma unroll
        for (int q = 0; q < NP; q++) {
            ep[q] += __shfl_xor_sync(0xFFFFFFFFu, ep[q], off);
            dp[q] += __shfl_xor_sync(0xFFFFFFFFu, dp[q], off);
        }
    }
    // lane 0 writes 2 packed entries (b3 offsets cancel in the slopes)
    if (lane == 0) {
        #pragma unroll
        for (int q = 0; q < NP - 1; q++)
            g_table[p0 + q] = make_float4(ep[q] + b3v, dp[q],
                                          ep[q + 1] - ep[q], dp[q + 1] - dp[q]);
    }
}

// ============================================================================
// Kernel 2: per-edge — dist, float4 table interp, scalar REDs, e/stress reduce
// ============================================================================
#define ETPB 256
#define EPT  4     // tile = 1024 edges; graphs are 98304-aligned (divisible by 128)

__global__ __launch_bounds__(ETPB)
void edge_kernel(const float* __restrict__ bv,
                 const int* __restrict__ src, const int* __restrict__ dst,
                 const int* __restrict__ eg, int E, int N)
{
    __shared__ float se[NG];
    __shared__ float ss[NG * 9];
    const int tid = threadIdx.x;
    if (tid < NG)     se[tid] = 0.0f;
    if (tid < NG * 9) ss[tid] = 0.0f;
    __syncthreads();

    const int lane = tid & 31;
    const int warp_base = blockIdx.x * (ETPB * EPT) + (tid >> 5) * (32 * EPT);
    // whole warp tile lies in one graph (tiles 128-aligned, graphs 98304-aligned)
    const int g0 = (warp_base < E) ? eg[warp_base] : 0;
    const bool full = (warp_base + 32 * EPT) <= E;

    float acc[10];
    #pragma unroll
    for (int q = 0; q < 10; q++) acc[q] = 0.0f;

    #pragma unroll
    for (int k = 0; k < EPT; k++) {
        const int e = warp_base + k * 32 + lane;
        if (!full && e >= E) break;
        const int ns = src[e], nd = dst[e];
        const float bx = bv[3*e+0], by = bv[3*e+1], bz = bv[3*e+2];
        const float4 pd = g_posw[nd];
        const float4 ps = g_posw[ns];
        const float dx = bx + pd.x - ps.x;
        const float dy = by + pd.y - ps.y;
        const float dz = bz + pd.z - ps.z;
        const float dist = sqrtf(dx*dx + dy*dy + dz*dz + 1e-12f);

        // table interp (clamp: beyond DMAX the fp32 reference is exactly constant)
        float s = fminf(dist * TBL_INVH, (float)TBL_N - 0.001f);
        const int   ti = (int)s;
        const float fr = s - (float)ti;
        const float4 tb = g_table[ti];
        const float ee = tb.x + fr * tb.z;
        const float dd = tb.y + fr * tb.w;

        const float sc = __fdividef(dd, dist);
        const float gx = sc * dx, gy = sc * dy, gz = sc * dz;  // gpos contribution

        atomicAdd(&g_scr[8 + 3*nd + 0],  gx);
        atomicAdd(&g_scr[8 + 3*nd + 1],  gy);
        atomicAdd(&g_scr[8 + 3*nd + 2],  gz);
        atomicAdd(&g_scr[8 + 3*ns + 0], -gx);
        atomicAdd(&g_scr[8 + 3*ns + 1], -gy);
        atomicAdd(&g_scr[8 + 3*ns + 2], -gz);

        const float fx = -gx, fy = -gy, fz = -gz;   // f_ij
        acc[0] += ee;
        acc[1] += bx*fx; acc[2] += bx*fy; acc[3] += bx*fz;
        acc[4] += by*fx; acc[5] += by*fy; acc[6] += by*fz;
        acc[7] += bz*fx; acc[8] += bz*fy; acc[9] += bz*fz;
    }

    // warp butterfly (whole warp shares graph g0 by construction)
    #pragma unroll
    for (int off = 16; off; off >>= 1) {
        #pragma unroll
        for (int q = 0; q < 10; q++)
            acc[q] += __shfl_xor_sync(0xFFFFFFFFu, acc[q], off);
    }
    if (lane == 0 && warp_base < E) {
        atomicAdd(&se[g0], acc[0]);
        #pragma unroll
        for (int q = 0; q < 9; q++) atomicAdd(&ss[g0*9 + q], acc[1 + q]);
    }

    __syncthreads();
    if (tid < NG)     atomicAdd(&g_scr[tid], se[tid]);
    if (tid < NG * 9) atomicAdd(&g_scr[8 + 3*N + tid], ss[tid]);
}

// ============================================================================
// Kernel 3: write every out element; re-zero scratch for graph replay
// ============================================================================
__global__ void finalize2(float* __restrict__ out, const float* __restrict__ volume,
                          int N, int out_size) {
    int i = blockIdx.x * blockDim.x + threadIdx.x;
    const int nf = 3 * N;
    if (i < 8) {
        out[i] = g_scr[i];
        g_scr[i] = 0.0f;
    } else if (i < 8 + nf) {
        out[i] = -g_scr[i];                        // forces = -gpos
        g_scr[i] = 0.0f;
    } else if (i < 8 + nf + 72) {
        int s = i - 8 - nf;
        int g = s / 9;
        float vol0 = volume[g * (N / NG)];
        out[i] = (-EV2GPA) * g_scr[i] / vol0;      // scaled stress
        g_scr[i] = 0.0f;
    } else if (i < out_size) {
        out[i] = 0.0f;                             // hessian
    }
}

extern "C" void kernel_launch(void* const* d_in, const int* in_sizes, int n_in,
                              void* d_out, int out_size) {
    const float* pos     = (const float*)d_in[0];
    const float* bv      = (const float*)d_in[1];
    const int*   src     = (const int*)  d_in[2];
    const int*   dst     = (const int*)  d_in[3];
    const int*   eg      = (const int*)  d_in[4];
    const float* volume  = (const float*)d_in[5];
    const float* centers = (const float*)d_in[6];
    const float* W1      = (const float*)d_in[7];
    const float* b1      = (const float*)d_in[8];
    const float* W2      = (const float*)d_in[9];
    const float* b2      = (const float*)d_in[10];
    const float* W3      = (const float*)d_in[11];
    const float* b3      = (const float*)d_in[12];
    float* out = (float*)d_out;

    const int N = in_sizes[0] / 3;
    const int E = in_sizes[1] / 3;

    pad_pos_kernel<<<(N + 255) / 256, 256>>>(pos, N);
    build_pts_kernel<<<BGRID, BTPB>>>(W1, b1, W2, b2, W3, b3, centers);
    edge_kernel<<<(E + ETPB * EPT - 1) / (ETPB * EPT), ETPB>>>(bv, src, dst, eg, E, N);
    finalize2<<<(out_size + 255) / 256, 256>>>(out, volume, N, out_size);
}